// round 3
// baseline (speedup 1.0000x reference)
#include <cuda_runtime.h>
#include <cstddef>

// Problem constants
#define B_  8
#define N_  1024
#define R_  16384
#define D_  32
#define E_  64
#define H_  512

// ---------------------------------------------------------------------------
// Scratch (device globals; no allocations allowed)
// ---------------------------------------------------------------------------
__device__ float g_node[(size_t)B_ * R_ * 64];   // [B*R, 64] node_obj; reused as h3
__device__ float g_h1 [(size_t)B_ * R_ * H_];    // [B*R, 512]
__device__ float g_h2 [(size_t)B_ * R_ * H_];    // [B*R, 512]
__device__ float g_edge[(size_t)B_ * R_ * E_];   // [B*R, 64]
__device__ float g_agg [(size_t)B_ * N_ * E_];   // [B*N, 64]
__device__ float g_upd [(size_t)B_ * N_ * (D_ + E_)]; // [B*N, 96]
__device__ float g_hn  [(size_t)B_ * N_ * H_];   // [B*N, 512]

// ---------------------------------------------------------------------------
// Gather: node[b*R+r, 0:32] = sum_n obj[b,n,:]*Rs[n,r]
//         node[b*R+r,32:64] = sum_n obj[b,n,:]*Rr[n,r]
// Block: 128 threads, each owns one r; tile n by 32.
// ---------------------------------------------------------------------------
__global__ __launch_bounds__(128)
void gather_kernel(const float* __restrict__ obj,
                   const float* __restrict__ Rs,
                   const float* __restrict__ Rr,
                   float* __restrict__ node)
{
    const int b  = blockIdx.y;
    const int tx = threadIdx.x;
    const int r  = blockIdx.x * 128 + tx;

    __shared__ float sS[32][128];
    __shared__ float sR[32][128];
    __shared__ float sO[32][32];

    float accS[32];
    float accD[32];
#pragma unroll
    for (int d = 0; d < 32; d++) { accS[d] = 0.f; accD[d] = 0.f; }

    const float* objb = obj + (size_t)b * N_ * D_;

    for (int n0 = 0; n0 < N_; n0 += 32) {
#pragma unroll 8
        for (int i = 0; i < 32; i++) {
            sS[i][tx] = Rs[(size_t)(n0 + i) * R_ + r];
            sR[i][tx] = Rr[(size_t)(n0 + i) * R_ + r];
        }
        for (int i = tx; i < 32 * 32; i += 128)
            sO[i >> 5][i & 31] = objb[(size_t)n0 * D_ + i];
        __syncthreads();

#pragma unroll
        for (int i = 0; i < 32; i++) {
            const float s = sS[i][tx];
            const float t = sR[i][tx];
            const float4* o4 = reinterpret_cast<const float4*>(&sO[i][0]);
#pragma unroll
            for (int q = 0; q < 8; q++) {
                float4 o = o4[q];
                accS[4*q+0] += s * o.x; accD[4*q+0] += t * o.x;
                accS[4*q+1] += s * o.y; accD[4*q+1] += t * o.y;
                accS[4*q+2] += s * o.z; accD[4*q+2] += t * o.z;
                accS[4*q+3] += s * o.w; accD[4*q+3] += t * o.w;
            }
        }
        __syncthreads();
    }

    float* out = node + ((size_t)b * R_ + r) * 64;
#pragma unroll
    for (int d = 0; d < 32; d++) { out[d] = accS[d]; out[32 + d] = accD[d]; }
}

// ---------------------------------------------------------------------------
// Generic tiled GEMM: C[m,n] = act( sum_k A[m,k]*W[k,n] + bias[n] )
// Row-major with explicit leading dims + batch strides (batch = blockIdx.z).
// ---------------------------------------------------------------------------
template<int BM, int BN, int BK, int TM, int TN, bool RELU>
__global__ __launch_bounds__((BM / TM) * (BN / TN))
void gemm_br(const float* __restrict__ A, const float* __restrict__ W,
             const float* __restrict__ bias, float* __restrict__ C,
             int M, int Nn, int K, int lda, int ldb, int ldc,
             size_t sA, size_t sB, size_t sC)
{
    constexpr int THREADS = (BM / TM) * (BN / TN);
    __shared__ float As[BK][BM + 4];
    __shared__ float Bs[BK][BN];

    const int bz = blockIdx.z;
    A += sA * bz; W += sB * bz; C += sC * bz;

    const int tid  = threadIdx.x;
    const int tcol = tid % (BN / TN);
    const int trow = tid / (BN / TN);
    const int m0 = blockIdx.y * BM;
    const int n0 = blockIdx.x * BN;

    float acc[TM][TN];
#pragma unroll
    for (int i = 0; i < TM; i++)
#pragma unroll
        for (int j = 0; j < TN; j++) acc[i][j] = 0.f;

    for (int k0 = 0; k0 < K; k0 += BK) {
        // A tile: BM x BK, stored transposed
#pragma unroll
        for (int idx = tid; idx < BM * BK; idx += THREADS) {
            int m = idx / BK, k = idx % BK;
            float v = 0.f;
            if (m0 + m < M && k0 + k < K) v = A[(size_t)(m0 + m) * lda + k0 + k];
            As[k][m] = v;
        }
        // B tile: BK x BN
#pragma unroll
        for (int idx = tid; idx < BK * BN; idx += THREADS) {
            int k = idx / BN, n = idx % BN;
            float v = 0.f;
            if (k0 + k < K && n0 + n < Nn) v = W[(size_t)(k0 + k) * ldb + n0 + n];
            Bs[k][n] = v;
        }
        __syncthreads();

#pragma unroll
        for (int k = 0; k < BK; k++) {
            float a[TM], b[TN];
#pragma unroll
            for (int i = 0; i < TM; i++) a[i] = As[k][trow * TM + i];
#pragma unroll
            for (int j = 0; j < TN; j++) b[j] = Bs[k][tcol * TN + j];
#pragma unroll
            for (int i = 0; i < TM; i++)
#pragma unroll
                for (int j = 0; j < TN; j++)
                    acc[i][j] += a[i] * b[j];
        }
        __syncthreads();
    }

#pragma unroll
    for (int i = 0; i < TM; i++) {
        int m = m0 + trow * TM + i;
        if (m >= M) continue;
#pragma unroll
        for (int j = 0; j < TN; j++) {
            int n = n0 + tcol * TN + j;
            if (n >= Nn) continue;
            float v = acc[i][j];
            if (bias) v += bias[n];
            if (RELU) v = fmaxf(v, 0.f);
            C[(size_t)m * ldc + n] = v;
        }
    }
}

// ---------------------------------------------------------------------------
// Concat: upd[b*N+n, 0:32] = obj ; [32:96] = agg
// ---------------------------------------------------------------------------
__global__ void concat_kernel(const float* __restrict__ obj,
                              const float* __restrict__ agg,
                              float* __restrict__ upd)
{
    int i = blockIdx.x * 256 + threadIdx.x;
    if (i >= B_ * N_ * 96) return;
    int j  = i % 96;
    int bn = i / 96;
    upd[i] = (j < 32) ? obj[(size_t)bn * 32 + j] : agg[(size_t)bn * 64 + (j - 32)];
}

// ---------------------------------------------------------------------------
// Host-side launch helpers
// ---------------------------------------------------------------------------
template<int BM, int BN, int BK, int TM, int TN, bool RELU>
static void run_gemm(const float* A, const float* W, const float* bias, float* C,
                     int M, int Nn, int K, int lda, int ldb, int ldc,
                     size_t sA, size_t sB, size_t sC, int batch)
{
    dim3 grid((Nn + BN - 1) / BN, (M + BM - 1) / BM, batch);
    gemm_br<BM, BN, BK, TM, TN, RELU>
        <<<grid, (BM / TM) * (BN / TN)>>>(A, W, bias, C, M, Nn, K,
                                          lda, ldb, ldc, sA, sB, sC);
}

extern "C" void kernel_launch(void* const* d_in, const int* in_sizes, int n_in,
                              void* d_out, int out_size)
{
    const float* obj = (const float*)d_in[0];
    const float* Rs  = (const float*)d_in[1];
    const float* Rr  = (const float*)d_in[2];
    const float* rw1 = (const float*)d_in[3];  const float* rb1 = (const float*)d_in[4];
    const float* rw2 = (const float*)d_in[5];  const float* rb2 = (const float*)d_in[6];
    const float* rw3 = (const float*)d_in[7];  const float* rb3 = (const float*)d_in[8];
    const float* rw4 = (const float*)d_in[9];  const float* rb4 = (const float*)d_in[10];
    const float* ow1 = (const float*)d_in[11]; const float* ob1 = (const float*)d_in[12];
    const float* ow2 = (const float*)d_in[13]; const float* ob2 = (const float*)d_in[14];
    float* out = (float*)d_out;

    float *node, *h1, *h2, *edge, *agg, *upd, *hn;
    cudaGetSymbolAddress((void**)&node, g_node);
    cudaGetSymbolAddress((void**)&h1,   g_h1);
    cudaGetSymbolAddress((void**)&h2,   g_h2);
    cudaGetSymbolAddress((void**)&edge, g_edge);
    cudaGetSymbolAddress((void**)&agg,  g_agg);
    cudaGetSymbolAddress((void**)&upd,  g_upd);
    cudaGetSymbolAddress((void**)&hn,   g_hn);

    const int MR = B_ * R_;   // 131072 edge rows
    const int MN = B_ * N_;   // 8192  node rows

    // 1) gather: node_obj [B*R, 64]
    gather_kernel<<<dim3(R_ / 128, B_), 128>>>(obj, Rs, Rr, node);

    // 2) edge MLP
    run_gemm<128,128,16,8,8,true >(node, rw1, rb1, h1,  MR, H_,  64, 64, H_,  H_, 0,0,0, 1);
    run_gemm<128,128,16,8,8,true >(h1,   rw2, rb2, h2,  MR, H_, H_, H_, H_,  H_, 0,0,0, 1);
    run_gemm<128, 64,16,8,4,true >(h2,   rw3, rb3, node,MR, E_, H_, H_, E_,  E_, 0,0,0, 1); // h3 -> reuse g_node
    run_gemm<128, 64,16,8,4,true >(node, rw4, rb4, edge,MR, E_,  64, 64, E_,  E_, 0,0,0, 1);

    // 3) scatter-aggregate: agg[b] = Rr[N,R] @ edge[b][R,64]   (batched over b)
    run_gemm< 64, 64,16,4,4,false>(Rr, edge, nullptr, agg,
                                   N_, E_, R_, R_, E_, E_,
                                   0, (size_t)R_ * E_, (size_t)N_ * E_, B_);

    // 4) node MLP
    concat_kernel<<<(B_ * N_ * 96 + 255) / 256, 256>>>(obj, agg, upd);
    run_gemm<128,128,16,8,8,true >(upd, ow1, ob1, hn,  MN, H_,  96, 96, H_,  H_, 0,0,0, 1);
    run_gemm<128, 32,16,8,4,false>(hn,  ow2, ob2, out, MN, D_, H_, H_, D_,  D_, 0,0,0, 1);
}

// round 4
// speedup vs baseline: 1.0081x; 1.0081x over previous
#include <cuda_runtime.h>
#include <cstddef>

// Problem constants
#define B_  8
#define N_  1024
#define R_  16384
#define D_  32
#define E_  64
#define H_  512

// ---------------------------------------------------------------------------
// Scratch (device globals; no allocations allowed)
// ---------------------------------------------------------------------------
__device__ float g_node[(size_t)B_ * R_ * 64];   // [B*R, 64] node_obj; reused as h3
__device__ float g_h1 [(size_t)B_ * R_ * H_];    // [B*R, 512]
__device__ float g_h2 [(size_t)B_ * R_ * H_];    // [B*R, 512]
__device__ float g_edge[(size_t)B_ * R_ * E_];   // [B*R, 64]
__device__ float g_agg [(size_t)B_ * N_ * E_];   // [B*N, 64]
__device__ float g_upd [(size_t)B_ * N_ * (D_ + E_)]; // [B*N, 96]
__device__ float g_hn  [(size_t)B_ * N_ * H_];   // [B*N, 512]

// ---------------------------------------------------------------------------
// Gather: node[b*R+r, 0:32] = sum_n obj[b,n,:]*Rs[n,r]
//         node[b*R+r,32:64] = sum_n obj[b,n,:]*Rr[n,r]
// Block: 128 threads, each owns one r; tile n by 32.
// ---------------------------------------------------------------------------
__global__ __launch_bounds__(128)
void gather_kernel(const float* __restrict__ obj,
                   const float* __restrict__ Rs,
                   const float* __restrict__ Rr,
                   float* __restrict__ node)
{
    const int b  = blockIdx.y;
    const int tx = threadIdx.x;
    const int r  = blockIdx.x * 128 + tx;

    __shared__ float sS[32][128];
    __shared__ float sR[32][128];
    __shared__ float sO[32][32];

    float accS[32];
    float accD[32];
#pragma unroll
    for (int d = 0; d < 32; d++) { accS[d] = 0.f; accD[d] = 0.f; }

    const float* objb = obj + (size_t)b * N_ * D_;

    for (int n0 = 0; n0 < N_; n0 += 32) {
#pragma unroll 8
        for (int i = 0; i < 32; i++) {
            sS[i][tx] = Rs[(size_t)(n0 + i) * R_ + r];
            sR[i][tx] = Rr[(size_t)(n0 + i) * R_ + r];
        }
        for (int i = tx; i < 32 * 32; i += 128)
            sO[i >> 5][i & 31] = objb[(size_t)n0 * D_ + i];
        __syncthreads();

#pragma unroll
        for (int i = 0; i < 32; i++) {
            const float s = sS[i][tx];
            const float t = sR[i][tx];
            const float4* o4 = reinterpret_cast<const float4*>(&sO[i][0]);
#pragma unroll
            for (int q = 0; q < 8; q++) {
                float4 o = o4[q];
                accS[4*q+0] += s * o.x; accD[4*q+0] += t * o.x;
                accS[4*q+1] += s * o.y; accD[4*q+1] += t * o.y;
                accS[4*q+2] += s * o.z; accD[4*q+2] += t * o.z;
                accS[4*q+3] += s * o.w; accD[4*q+3] += t * o.w;
            }
        }
        __syncthreads();
    }

    float* out = node + ((size_t)b * R_ + r) * 64;
#pragma unroll
    for (int d = 0; d < 32; d++) { out[d] = accS[d]; out[32 + d] = accD[d]; }
}

// ---------------------------------------------------------------------------
// Generic tiled GEMM: C[m,n] = act( sum_k A[m,k]*W[k,n] + bias[n] )
// Row-major with explicit leading dims + batch strides (batch = blockIdx.z).
// ---------------------------------------------------------------------------
template<int BM, int BN, int BK, int TM, int TN, bool RELU>
__global__ __launch_bounds__((BM / TM) * (BN / TN))
void gemm_br(const float* __restrict__ A, const float* __restrict__ W,
             const float* __restrict__ bias, float* __restrict__ C,
             int M, int Nn, int K, int lda, int ldb, int ldc,
             size_t sA, size_t sB, size_t sC)
{
    constexpr int THREADS = (BM / TM) * (BN / TN);
    __shared__ float As[BK][BM + 4];
    __shared__ float Bs[BK][BN];

    const int bz = blockIdx.z;
    A += sA * bz; W += sB * bz; C += sC * bz;

    const int tid  = threadIdx.x;
    const int tcol = tid % (BN / TN);
    const int trow = tid / (BN / TN);
    const int m0 = blockIdx.y * BM;
    const int n0 = blockIdx.x * BN;

    float acc[TM][TN];
#pragma unroll
    for (int i = 0; i < TM; i++)
#pragma unroll
        for (int j = 0; j < TN; j++) acc[i][j] = 0.f;

    for (int k0 = 0; k0 < K; k0 += BK) {
        // A tile: BM x BK, stored transposed
#pragma unroll
        for (int idx = tid; idx < BM * BK; idx += THREADS) {
            int m = idx / BK, k = idx % BK;
            float v = 0.f;
            if (m0 + m < M && k0 + k < K) v = A[(size_t)(m0 + m) * lda + k0 + k];
            As[k][m] = v;
        }
        // B tile: BK x BN
#pragma unroll
        for (int idx = tid; idx < BK * BN; idx += THREADS) {
            int k = idx / BN, n = idx % BN;
            float v = 0.f;
            if (k0 + k < K && n0 + n < Nn) v = W[(size_t)(k0 + k) * ldb + n0 + n];
            Bs[k][n] = v;
        }
        __syncthreads();

#pragma unroll
        for (int k = 0; k < BK; k++) {
            float a[TM], b[TN];
#pragma unroll
            for (int i = 0; i < TM; i++) a[i] = As[k][trow * TM + i];
#pragma unroll
            for (int j = 0; j < TN; j++) b[j] = Bs[k][tcol * TN + j];
#pragma unroll
            for (int i = 0; i < TM; i++)
#pragma unroll
                for (int j = 0; j < TN; j++)
                    acc[i][j] += a[i] * b[j];
        }
        __syncthreads();
    }

#pragma unroll
    for (int i = 0; i < TM; i++) {
        int m = m0 + trow * TM + i;
        if (m >= M) continue;
#pragma unroll
        for (int j = 0; j < TN; j++) {
            int n = n0 + tcol * TN + j;
            if (n >= Nn) continue;
            float v = acc[i][j];
            if (bias) v += bias[n];
            if (RELU) v = fmaxf(v, 0.f);
            C[(size_t)m * ldc + n] = v;
        }
    }
}

// ---------------------------------------------------------------------------
// Concat: upd[b*N+n, 0:32] = obj ; [32:96] = agg
// ---------------------------------------------------------------------------
__global__ void concat_kernel(const float* __restrict__ obj,
                              const float* __restrict__ agg,
                              float* __restrict__ upd)
{
    int i = blockIdx.x * 256 + threadIdx.x;
    if (i >= B_ * N_ * 96) return;
    int j  = i % 96;
    int bn = i / 96;
    upd[i] = (j < 32) ? obj[(size_t)bn * 32 + j] : agg[(size_t)bn * 64 + (j - 32)];
}

// ---------------------------------------------------------------------------
// Host-side launch helpers
// ---------------------------------------------------------------------------
template<int BM, int BN, int BK, int TM, int TN, bool RELU>
static void run_gemm(const float* A, const float* W, const float* bias, float* C,
                     int M, int Nn, int K, int lda, int ldb, int ldc,
                     size_t sA, size_t sB, size_t sC, int batch)
{
    dim3 grid((Nn + BN - 1) / BN, (M + BM - 1) / BM, batch);
    gemm_br<BM, BN, BK, TM, TN, RELU>
        <<<grid, (BM / TM) * (BN / TN)>>>(A, W, bias, C, M, Nn, K,
                                          lda, ldb, ldc, sA, sB, sC);
}

extern "C" void kernel_launch(void* const* d_in, const int* in_sizes, int n_in,
                              void* d_out, int out_size)
{
    const float* obj = (const float*)d_in[0];
    const float* Rs  = (const float*)d_in[1];
    const float* Rr  = (const float*)d_in[2];
    const float* rw1 = (const float*)d_in[3];  const float* rb1 = (const float*)d_in[4];
    const float* rw2 = (const float*)d_in[5];  const float* rb2 = (const float*)d_in[6];
    const float* rw3 = (const float*)d_in[7];  const float* rb3 = (const float*)d_in[8];
    const float* rw4 = (const float*)d_in[9];  const float* rb4 = (const float*)d_in[10];
    const float* ow1 = (const float*)d_in[11]; const float* ob1 = (const float*)d_in[12];
    const float* ow2 = (const float*)d_in[13]; const float* ob2 = (const float*)d_in[14];
    float* out = (float*)d_out;

    float *node, *h1, *h2, *edge, *agg, *upd, *hn;
    cudaGetSymbolAddress((void**)&node, g_node);
    cudaGetSymbolAddress((void**)&h1,   g_h1);
    cudaGetSymbolAddress((void**)&h2,   g_h2);
    cudaGetSymbolAddress((void**)&edge, g_edge);
    cudaGetSymbolAddress((void**)&agg,  g_agg);
    cudaGetSymbolAddress((void**)&upd,  g_upd);
    cudaGetSymbolAddress((void**)&hn,   g_hn);

    const int MR = B_ * R_;   // 131072 edge rows
    const int MN = B_ * N_;   // 8192  node rows

    // 1) gather: node_obj [B*R, 64]
    gather_kernel<<<dim3(R_ / 128, B_), 128>>>(obj, Rs, Rr, node);

    // 2) edge MLP
    run_gemm<128,128,16,8,8,true >(node, rw1, rb1, h1,  MR, H_,  64, 64, H_,  H_, 0,0,0, 1);
    run_gemm<128,128,16,8,8,true >(h1,   rw2, rb2, h2,  MR, H_, H_, H_, H_,  H_, 0,0,0, 1);
    run_gemm<128, 64,16,8,4,true >(h2,   rw3, rb3, node,MR, E_, H_, H_, E_,  E_, 0,0,0, 1); // h3 -> reuse g_node
    run_gemm<128, 64,16,8,4,true >(node, rw4, rb4, edge,MR, E_,  64, 64, E_,  E_, 0,0,0, 1);

    // 3) scatter-aggregate: agg[b] = Rr[N,R] @ edge[b][R,64]   (batched over b)
    run_gemm< 64, 64,16,4,4,false>(Rr, edge, nullptr, agg,
                                   N_, E_, R_, R_, E_, E_,
                                   0, (size_t)R_ * E_, (size_t)N_ * E_, B_);

    // 4) node MLP
    concat_kernel<<<(B_ * N_ * 96 + 255) / 256, 256>>>(obj, agg, upd);
    run_gemm<128,128,16,8,8,true >(upd, ow1, ob1, hn,  MN, H_,  96, 96, H_,  H_, 0,0,0, 1);
    run_gemm<128, 32,16,8,4,false>(hn,  ow2, ob2, out, MN, D_, H_, H_, D_,  D_, 0,0,0, 1);
}